// round 10
// baseline (speedup 1.0000x reference)
#include <cuda_runtime.h>
#include <cuda_bf16.h>
#include <cstdint>

// vaeVectorQuantizer: x[N=131072, D=64], E[D=64, K=1024]
// 2-limb bf16 split, 3 limb products (x1e1, x1e2, x2e1) via mma.sync.m16n8k16.
// Key error ~1e-5 worst case => per-row top-2 tracking + exact fp32 rescore of
// both candidates when gap < EPS. y_sq/e_sq correctly rounded (double).

#define D_DIM 64
#define K_DIM 1024
#define ROWS_PER_CTA 128
#define NTILE 128
#define NTILES 8
#define NTHREADS 256
#define EPS 4e-4f

#define PADROW 144                             // 128B data + 16B pad
#define LIMB_STRIDE (ROWS_PER_CTA * PADROW)    // 18432
#define SM_X     0
#define SM_B     (2 * LIMB_STRIDE)             // 36864
#define B_BYTES  (NTILE * 64 * 2 * 2)          // 32768 (fragment-packed tile)
#define SM_ESQ   (SM_B + B_BYTES)              // 69632
#define SM_YS    (SM_ESQ + 4096)               // 73728
#define SM_MRG   (SM_YS + 512)                 // 74240 (2 halves x {v1,c1,v2,c2} x 128)
#define SM_CIDX  (SM_MRG + 4096)               // 78336
#define SM_TOTAL (SM_CIDX + 512)               // 78848

__device__ float g_esq[K_DIM];
__device__ float g_ET[K_DIM * D_DIM];             // [k][d] fp32, gather + rescore
__device__ uint2 g_Bf[NTILES * 4 * 2 * 16 * 32];  // [t][kc][limb][nf][lane]

__device__ __forceinline__ void split2(float f, __nv_bfloat16& b1, __nv_bfloat16& b2) {
    b1 = __float2bfloat16(f);
    b2 = __float2bfloat16(f - __bfloat162float(b1));
}

__device__ __forceinline__ void mma16816(float* c, uint32_t a0, uint32_t a1,
                                         uint32_t a2, uint32_t a3,
                                         uint32_t b0, uint32_t b1) {
    asm volatile(
        "mma.sync.aligned.m16n8k16.row.col.f32.bf16.bf16.f32 "
        "{%0,%1,%2,%3}, {%4,%5,%6,%7}, {%8,%9}, {%0,%1,%2,%3};"
        : "+f"(c[0]), "+f"(c[1]), "+f"(c[2]), "+f"(c[3])
        : "r"(a0), "r"(a1), "r"(a2), "r"(a3), "r"(b0), "r"(b1));
}

// top-2 update, lexicographic (value, index) so ties -> lowest index
__device__ __forceinline__ void upd2(float k, int c, float& v1, int& c1,
                                     float& v2, int& c2) {
    if (k < v1 || (k == v1 && c < c1)) { v2 = v1; c2 = c1; v1 = k; c1 = c; }
    else if (k < v2 || (k == v2 && c < c2)) { v2 = k; c2 = c; }
}

// ---------------- prep: e_sq via warp-per-code (parallel, fast) ----------------
__global__ void vq_prep(const float* __restrict__ E) {
    int wid = threadIdx.x >> 5, lane = threadIdx.x & 31;
    int k = blockIdx.x * 8 + wid;
    float v0 = E[lane * K_DIM + k];
    float v1 = E[(lane + 32) * K_DIM + k];
    g_ET[k * D_DIM + lane]      = v0;
    g_ET[k * D_DIM + lane + 32] = v1;
    double s = fma((double)v0, (double)v0, (double)v1 * (double)v1);
#pragma unroll
    for (int off = 16; off >= 1; off >>= 1)
        s += __shfl_xor_sync(0xffffffffu, s, off);
    if (lane == 0) g_esq[k] = (float)s;
}

// ---------------- prep: B limbs packed in mma fragment-lane order ----------------
// Fragment (t,kc,limb,nf), lane l, reg m, half j holds
//   E_limb[d][code],  d = kc*16 + (l%4)*2 + m*8 + j,  code = t*128 + nf*8 + l/4
__global__ void vq_prep_b(const float* __restrict__ E) {
    int idx = blockIdx.x * blockDim.x + threadIdx.x;   // 32768 total
    int lane = idx & 31;
    int x1 = idx >> 5;
    int nf = x1 & 15;
    int x2 = x1 >> 4;
    int limb = x2 & 1;
    int x3 = x2 >> 1;
    int kc = x3 & 3;
    int t = x3 >> 2;

    int code = t * 128 + nf * 8 + (lane >> 2);
    int c = lane & 3;
    uint32_t r[2];
#pragma unroll
    for (int m = 0; m < 2; ++m) {
        int d0 = kc * 16 + c * 2 + m * 8;
        __nv_bfloat16 q0[2], q1[2];
        split2(E[d0 * K_DIM + code], q0[0], q0[1]);
        split2(E[(d0 + 1) * K_DIM + code], q1[0], q1[1]);
        __nv_bfloat162 pk(q0[limb], q1[limb]);
        r[m] = *(uint32_t*)&pk;
    }
    g_Bf[idx] = make_uint2(r[0], r[1]);
}

// ---------------- main ----------------
__global__ __launch_bounds__(NTHREADS, 2)
void vq_tc(const float* __restrict__ x, float* __restrict__ out) {
    extern __shared__ __align__(16) char smem[];
    const int tid = threadIdx.x;
    const int wid = tid >> 5;
    const int lane = tid & 31;
    const size_t rowbase = (size_t)blockIdx.x * ROWS_PER_CTA;

    float* esq_s = (float*)(smem + SM_ESQ);
    float* ys_sh = (float*)(smem + SM_YS);
    int*   cidx  = (int*)(smem + SM_CIDX);

    *(float4*)(esq_s + 4 * tid) = *(const float4*)(g_esq + 4 * tid);

    // ---- x: 2-limb bf16 split into padded smem + exact double row norms
    {
        int r = tid >> 1, dh = (tid & 1) * 32;
        const float* xr = x + (rowbase + r) * D_DIM + dh;
        char* xs = smem + SM_X + r * PADROW;
        double s = 0.0;
#pragma unroll
        for (int i = 0; i < 8; ++i) {
            float4 v = *(const float4*)(xr + 4 * i);
            int d0 = dh + 4 * i;
            float vs[4] = {v.x, v.y, v.z, v.w};
            __nv_bfloat16 p1[4], p2[4];
#pragma unroll
            for (int e = 0; e < 4; ++e) {
                split2(vs[e], p1[e], p2[e]);
                s = fma((double)vs[e], (double)vs[e], s);
            }
#pragma unroll
            for (int h = 0; h < 2; ++h) {
                int off = (d0 + 2 * h) * 2;
                *(__nv_bfloat162*)(xs + off)               = __nv_bfloat162(p1[2*h], p1[2*h+1]);
                *(__nv_bfloat162*)(xs + off + LIMB_STRIDE) = __nv_bfloat162(p2[2*h], p2[2*h+1]);
            }
        }
        s += __shfl_xor_sync(0xffffffffu, s, 1);
        if (!(tid & 1)) ys_sh[r] = (float)s;
    }
    __syncthreads();

    // Column-half split: warps 0-3 -> nf 0-7, warps 4-7 -> nf 8-15.
    const int colhalf = wid >> 2;
    const int wg = wid & 3;
    const int g = lane >> 2, c = lane & 3;

    int rowid[2][2];
    float ysr[2][2];
    const char* aRow[2][2];
#pragma unroll
    for (int mf = 0; mf < 2; ++mf)
#pragma unroll
        for (int h = 0; h < 2; ++h) {
            int r = wg * 32 + mf * 16 + h * 8 + g;
            rowid[mf][h] = r;
            ysr[mf][h] = ys_sh[r];
            aRow[mf][h] = smem + SM_X + r * PADROW + c * 4;
        }

    float v1[2][2] = {{3.402823466e38f, 3.402823466e38f},
                      {3.402823466e38f, 3.402823466e38f}};
    float v2[2][2] = {{3.402823466e38f, 3.402823466e38f},
                      {3.402823466e38f, 3.402823466e38f}};
    int   c1[2][2] = {{0, 0}, {0, 0}};
    int   c2[2][2] = {{0, 0}, {0, 0}};

    const int pp[3] = {0, 0, 1};
    const int qq[3] = {0, 1, 0};

    for (int t = 0; t < NTILES; ++t) {
        // ---- stage fragment-packed B tile (32KB) into smem
        const float4* gB = (const float4*)((const char*)g_Bf + t * B_BYTES);
        float4* sB = (float4*)(smem + SM_B);
#pragma unroll
        for (int i = 0; i < 8; ++i) sB[tid + i * NTHREADS] = __ldg(gB + tid + i * NTHREADS);
        __syncthreads();

        float acc[8][2][4];
#pragma unroll
        for (int nf = 0; nf < 8; ++nf)
#pragma unroll
            for (int mf = 0; mf < 2; ++mf)
#pragma unroll
                for (int j = 0; j < 4; ++j) acc[nf][mf][j] = 0.f;

#pragma unroll
        for (int kc = 0; kc < 4; ++kc) {
#pragma unroll
            for (int pr = 0; pr < 3; ++pr) {
                const int p = pp[pr], q = qq[pr];
                const uint2* bp = (const uint2*)(smem + SM_B + (kc * 2 + q) * 4096)
                                  + colhalf * 256 + lane;
                uint2 B[8];
#pragma unroll
                for (int nf = 0; nf < 8; ++nf) B[nf] = bp[nf * 32];
#pragma unroll
                for (int mf = 0; mf < 2; ++mf) {
                    const char* a0p = aRow[mf][0] + p * LIMB_STRIDE + kc * 32;
                    const char* a1p = aRow[mf][1] + p * LIMB_STRIDE + kc * 32;
                    uint32_t a0 = *(const uint32_t*)(a0p);
                    uint32_t a1 = *(const uint32_t*)(a1p);
                    uint32_t a2 = *(const uint32_t*)(a0p + 16);
                    uint32_t a3 = *(const uint32_t*)(a1p + 16);
#pragma unroll
                    for (int nf = 0; nf < 8; ++nf)
                        mma16816(acc[nf][mf], a0, a1, a2, a3, B[nf].x, B[nf].y);
                }
            }
        }

        // ---- epilogue: top-2 per row-slot
#pragma unroll
        for (int nf = 0; nf < 8; ++nf) {
            int cb = t * NTILE + colhalf * 64 + nf * 8 + 2 * c;
            float e0 = esq_s[cb], e1 = esq_s[cb + 1];
#pragma unroll
            for (int mf = 0; mf < 2; ++mf) {
                float k00 = fmaf(-2.f, acc[nf][mf][0], __fadd_rn(ysr[mf][0], e0));
                float k01 = fmaf(-2.f, acc[nf][mf][1], __fadd_rn(ysr[mf][0], e1));
                float k10 = fmaf(-2.f, acc[nf][mf][2], __fadd_rn(ysr[mf][1], e0));
                float k11 = fmaf(-2.f, acc[nf][mf][3], __fadd_rn(ysr[mf][1], e1));
                upd2(k00, cb,     v1[mf][0], c1[mf][0], v2[mf][0], c2[mf][0]);
                upd2(k01, cb + 1, v1[mf][0], c1[mf][0], v2[mf][0], c2[mf][0]);
                upd2(k10, cb,     v1[mf][1], c1[mf][1], v2[mf][1], c2[mf][1]);
                upd2(k11, cb + 1, v1[mf][1], c1[mf][1], v2[mf][1], c2[mf][1]);
            }
        }
        __syncthreads();   // B tile consumed before next stage overwrites
    }

    // ---- merge top-2 across the 4 lanes (c) sharing each row
#pragma unroll
    for (int off = 1; off <= 2; off <<= 1) {
#pragma unroll
        for (int mf = 0; mf < 2; ++mf)
#pragma unroll
            for (int h = 0; h < 2; ++h) {
                float ov1 = __shfl_xor_sync(0xffffffffu, v1[mf][h], off);
                int   oc1 = __shfl_xor_sync(0xffffffffu, c1[mf][h], off);
                float ov2 = __shfl_xor_sync(0xffffffffu, v2[mf][h], off);
                int   oc2 = __shfl_xor_sync(0xffffffffu, c2[mf][h], off);
                upd2(ov1, oc1, v1[mf][h], c1[mf][h], v2[mf][h], c2[mf][h]);
                upd2(ov2, oc2, v1[mf][h], c1[mf][h], v2[mf][h], c2[mf][h]);
            }
    }
    // ---- publish per-half top-2, merge across halves
    float* hv1 = (float*)(smem + SM_MRG);          // [half][row]
    int*   hc1 = (int*)(smem + SM_MRG + 1024);
    float* hv2 = (float*)(smem + SM_MRG + 2048);
    int*   hc2 = (int*)(smem + SM_MRG + 3072);
    if (c == 0) {
#pragma unroll
        for (int mf = 0; mf < 2; ++mf)
#pragma unroll
            for (int h = 0; h < 2; ++h) {
                int r = colhalf * 128 + rowid[mf][h];
                hv1[r] = v1[mf][h]; hc1[r] = c1[mf][h];
                hv2[r] = v2[mf][h]; hc2[r] = c2[mf][h];
            }
    }
    __syncthreads();
    if (tid < ROWS_PER_CTA) {
        float V1 = hv1[tid]; int C1 = hc1[tid];
        float V2 = hv2[tid]; int C2 = hc2[tid];
        upd2(hv1[128 + tid], hc1[128 + tid], V1, C1, V2, C2);
        upd2(hv2[128 + tid], hc2[128 + tid], V1, C1, V2, C2);
        int pick = C1;
        if (V2 - V1 < EPS) {
            // exact rescore of the two candidates (fp32, reference rounding)
            const float* xr = x + (rowbase + tid) * D_DIM;
            const float* eA = g_ET + C1 * D_DIM;
            const float* eB = g_ET + C2 * D_DIM;
            float dA = 0.f, dB = 0.f;
#pragma unroll
            for (int d = 0; d < D_DIM; ++d) {
                float xv = xr[d];
                dA = fmaf(xv, eA[d], dA);
                dB = fmaf(xv, eB[d], dB);
            }
            float ys = ys_sh[tid];
            float kA = fmaf(-2.f, dA, __fadd_rn(ys, esq_s[C1]));
            float kB = fmaf(-2.f, dB, __fadd_rn(ys, esq_s[C2]));
            if (kB < kA || (kB == kA && C2 < C1)) pick = C2;
        }
        cidx[tid] = pick;
    }
    __syncthreads();

    // ---- gather output rows from transposed codebook
    float* og = out + rowbase * D_DIM;
#pragma unroll
    for (int it = 0; it < 8; ++it) {
        int i  = tid + it * NTHREADS;
        int r  = i >> 4;
        int d0 = (i & 15) << 2;
        *(float4*)(og + r * D_DIM + d0) = *(const float4*)(g_ET + cidx[r] * D_DIM + d0);
    }
}

extern "C" void kernel_launch(void* const* d_in, const int* in_sizes, int n_in,
                              void* d_out, int out_size) {
    const float* x = (const float*)d_in[0];
    const float* E = (const float*)d_in[1];
    float* out = (float*)d_out;
    int N = in_sizes[0] / D_DIM;  // 131072

    cudaFuncSetAttribute(vq_tc, cudaFuncAttributeMaxDynamicSharedMemorySize, SM_TOTAL);
    vq_prep<<<K_DIM / 8, NTHREADS>>>(E);
    vq_prep_b<<<(NTILES * 4 * 2 * 16 * 32) / NTHREADS, NTHREADS>>>(E);
    vq_tc<<<N / ROWS_PER_CTA, NTHREADS, SM_TOTAL>>>(x, out);
}

// round 11
// speedup vs baseline: 1.3873x; 1.3873x over previous
#include <cuda_runtime.h>
#include <cuda_bf16.h>
#include <cstdint>

// vaeVectorQuantizer: x[N=131072, D=64], E[D=64, K=1024]
// mma.sync.m16n8k16.bf16; sim = 6 limb products of 3-limb bf16 splits
// (exact class: measured rel_err=0.0 in R8). key = fmaf(-2,sim, fl(y_sq+e_sq)),
// y_sq/e_sq correctly rounded via double, ties -> lowest index.
// R10 changes: A-limb register caching (smem traffic /2) + cp.async
// double-buffered B tiles (stage/compute overlap); occupancy-1 reg budget.

#define D_DIM 64
#define K_DIM 1024
#define ROWS_PER_CTA 128
#define NTILE 128
#define NTILES 8
#define NTHREADS 256

#define PADROW 144                             // 128B data + 16B pad
#define LIMB_STRIDE (ROWS_PER_CTA * PADROW)    // 18432
#define SM_X     0
#define SM_B     (3 * LIMB_STRIDE)             // 55296
#define B_BYTES  (NTILE * 64 * 3 * 2)          // 49152 per tile (fragment-packed)
#define SM_ESQ   (SM_B + 2 * B_BYTES)          // 153600 (double buffer)
#define SM_YS    (SM_ESQ + 4096)               // 157696
#define SM_MRG   (SM_YS + 512)                 // 158208
#define SM_CIDX  (SM_MRG + 2048)               // 160256
#define SM_TOTAL (SM_CIDX + 512)               // 160768

__device__ float g_esq[K_DIM];
__device__ float g_ET[K_DIM * D_DIM];             // [k][d] for coalesced gather
__device__ uint2 g_Bf[NTILES * 4 * 3 * 16 * 32];  // [t][kc][limb][nf][lane]

__device__ __forceinline__ uint32_t smem_u32(const void* p) {
    uint32_t a;
    asm("{ .reg .u64 t; cvta.to.shared.u64 t, %1; cvt.u32.u64 %0, t; }" : "=r"(a) : "l"(p));
    return a;
}
__device__ __forceinline__ void cp16(uint32_t dst, const void* src) {
    asm volatile("cp.async.cg.shared.global [%0], [%1], 16;" :: "r"(dst), "l"(src));
}
#define CP_COMMIT() asm volatile("cp.async.commit_group;" ::: "memory")
#define CP_WAIT(N)  asm volatile("cp.async.wait_group %0;" :: "n"(N) : "memory")

__device__ __forceinline__ void split3(float f, __nv_bfloat16& b1,
                                       __nv_bfloat16& b2, __nv_bfloat16& b3) {
    b1 = __float2bfloat16(f);
    float r1 = f - __bfloat162float(b1);
    b2 = __float2bfloat16(r1);
    float r2 = r1 - __bfloat162float(b2);
    b3 = __float2bfloat16(r2);
}

__device__ __forceinline__ void mma16816(float* c, uint32_t a0, uint32_t a1,
                                         uint32_t a2, uint32_t a3,
                                         uint32_t b0, uint32_t b1) {
    asm volatile(
        "mma.sync.aligned.m16n8k16.row.col.f32.bf16.bf16.f32 "
        "{%0,%1,%2,%3}, {%4,%5,%6,%7}, {%8,%9}, {%0,%1,%2,%3};"
        : "+f"(c[0]), "+f"(c[1]), "+f"(c[2]), "+f"(c[3])
        : "r"(a0), "r"(a1), "r"(a2), "r"(a3), "r"(b0), "r"(b1));
}

// ---------------- prep: e_sq via warp-per-code + transposed gather table ----------------
__global__ void vq_prep(const float* __restrict__ E) {
    int wid = threadIdx.x >> 5, lane = threadIdx.x & 31;
    int k = blockIdx.x * 8 + wid;
    float v0 = E[lane * K_DIM + k];
    float v1 = E[(lane + 32) * K_DIM + k];
    g_ET[k * D_DIM + lane]      = v0;
    g_ET[k * D_DIM + lane + 32] = v1;
    double s = fma((double)v0, (double)v0, (double)v1 * (double)v1);
#pragma unroll
    for (int off = 16; off >= 1; off >>= 1)
        s += __shfl_xor_sync(0xffffffffu, s, off);
    if (lane == 0) g_esq[k] = (float)s;
}

// ---------------- prep: B limbs packed in mma fragment-lane order ----------------
// Fragment (t,kc,limb,nf), lane l, reg m, half j holds
//   E_limb[d][code],  d = kc*16 + (l%4)*2 + m*8 + j,  code = t*128 + nf*8 + l/4
__global__ void vq_prep_b(const float* __restrict__ E) {
    int idx = blockIdx.x * blockDim.x + threadIdx.x;   // 49152 total
    int lane = idx & 31;
    int x1 = idx >> 5;
    int nf = x1 & 15;
    int x2 = x1 >> 4;
    int limb = x2 % 3;
    int x3 = x2 / 3;
    int kc = x3 & 3;
    int t = x3 >> 2;

    int code = t * 128 + nf * 8 + (lane >> 2);
    int c = lane & 3;
    uint32_t r[2];
#pragma unroll
    for (int m = 0; m < 2; ++m) {
        int d0 = kc * 16 + c * 2 + m * 8;
        __nv_bfloat16 q0[3], q1[3];
        split3(E[d0 * K_DIM + code], q0[0], q0[1], q0[2]);
        split3(E[(d0 + 1) * K_DIM + code], q1[0], q1[1], q1[2]);
        __nv_bfloat162 pk(q0[limb], q1[limb]);
        r[m] = *(uint32_t*)&pk;
    }
    g_Bf[idx] = make_uint2(r[0], r[1]);
}

// ---------------- main ----------------
__global__ __launch_bounds__(NTHREADS)
void vq_tc(const float* __restrict__ x, float* __restrict__ out) {
    extern __shared__ __align__(16) char smem[];
    const int tid = threadIdx.x;
    const int wid = tid >> 5;
    const int lane = tid & 31;
    const size_t rowbase = (size_t)blockIdx.x * ROWS_PER_CTA;

    float* esq_s = (float*)(smem + SM_ESQ);
    float* ys_sh = (float*)(smem + SM_YS);
    int*   cidx  = (int*)(smem + SM_CIDX);
    const uint32_t sB_u32 = smem_u32(smem + SM_B);

    *(float4*)(esq_s + 4 * tid) = *(const float4*)(g_esq + 4 * tid);

    // ---- prefetch B tile 0 into buffer 0 (overlaps the x-split below)
    {
        const char* src = (const char*)g_Bf;
#pragma unroll
        for (int i = 0; i < 12; ++i)
            cp16(sB_u32 + i * 4096 + tid * 16, src + i * 4096 + tid * 16);
        CP_COMMIT();
    }

    // ---- x: 3-limb bf16 split into padded smem + exact double row norms
    {
        int r = tid >> 1, dh = (tid & 1) * 32;
        const float* xr = x + (rowbase + r) * D_DIM + dh;
        char* xs = smem + SM_X + r * PADROW;
        double s = 0.0;
#pragma unroll
        for (int i = 0; i < 8; ++i) {
            float4 v = *(const float4*)(xr + 4 * i);
            int d0 = dh + 4 * i;
            float vs[4] = {v.x, v.y, v.z, v.w};
            __nv_bfloat16 p1[4], p2[4], p3[4];
#pragma unroll
            for (int e = 0; e < 4; ++e) {
                split3(vs[e], p1[e], p2[e], p3[e]);
                s = fma((double)vs[e], (double)vs[e], s);
            }
#pragma unroll
            for (int h = 0; h < 2; ++h) {
                int off = (d0 + 2 * h) * 2;
                *(__nv_bfloat162*)(xs + off)                   = __nv_bfloat162(p1[2*h], p1[2*h+1]);
                *(__nv_bfloat162*)(xs + off + LIMB_STRIDE)     = __nv_bfloat162(p2[2*h], p2[2*h+1]);
                *(__nv_bfloat162*)(xs + off + 2 * LIMB_STRIDE) = __nv_bfloat162(p3[2*h], p3[2*h+1]);
            }
        }
        s += __shfl_xor_sync(0xffffffffu, s, 1);
        if (!(tid & 1)) ys_sh[r] = (float)s;
    }

    // Column-half split: warps 0-3 -> nf 0-7, warps 4-7 -> nf 8-15.
    const int colhalf = wid >> 2;
    const int wg = wid & 3;
    const int g = lane >> 2, c = lane & 3;

    __syncthreads();   // x-split + ys visible

    int rowid[2][2];
    float ysr[2][2];
    const char* aRow[2][2];
#pragma unroll
    for (int mf = 0; mf < 2; ++mf)
#pragma unroll
        for (int h = 0; h < 2; ++h) {
            int r = wg * 32 + mf * 16 + h * 8 + g;
            rowid[mf][h] = r;
            ysr[mf][h] = ys_sh[r];
            aRow[mf][h] = smem + SM_X + r * PADROW + c * 4;
        }

    float bv[2][2] = {{3.402823466e38f, 3.402823466e38f},
                      {3.402823466e38f, 3.402823466e38f}};
    int   bc[2][2] = {{0, 0}, {0, 0}};

    for (int t = 0; t < NTILES; ++t) {
        const int buf = t & 1;
        // ---- prefetch next tile into the other buffer, then wait for current
        if (t + 1 < NTILES) {
            const char* src = (const char*)g_Bf + (t + 1) * B_BYTES;
            uint32_t dst = sB_u32 + (buf ^ 1) * B_BYTES;
#pragma unroll
            for (int i = 0; i < 12; ++i)
                cp16(dst + i * 4096 + tid * 16, src + i * 4096 + tid * 16);
            CP_COMMIT();
            CP_WAIT(1);     // current tile (older group) complete
        } else {
            CP_WAIT(0);
        }
        __syncthreads();

        float acc[8][2][4];
#pragma unroll
        for (int nf = 0; nf < 8; ++nf)
#pragma unroll
            for (int mf = 0; mf < 2; ++mf)
#pragma unroll
                for (int j = 0; j < 4; ++j) acc[nf][mf][j] = 0.f;

#pragma unroll
        for (int kc = 0; kc < 4; ++kc) {
            // ---- cache all A limb fragments for this kc (loaded once)
            uint32_t A[2][3][4];
#pragma unroll
            for (int mf = 0; mf < 2; ++mf)
#pragma unroll
                for (int p = 0; p < 3; ++p) {
                    const char* a0p = aRow[mf][0] + p * LIMB_STRIDE + kc * 32;
                    const char* a1p = aRow[mf][1] + p * LIMB_STRIDE + kc * 32;
                    A[mf][p][0] = *(const uint32_t*)(a0p);
                    A[mf][p][1] = *(const uint32_t*)(a1p);
                    A[mf][p][2] = *(const uint32_t*)(a0p + 16);
                    A[mf][p][3] = *(const uint32_t*)(a1p + 16);
                }
            // ---- per B limb q: load fragments once, fire all pairs (p < 3-q)
#pragma unroll
            for (int q = 0; q < 3; ++q) {
                const uint2* bp = (const uint2*)(smem + SM_B + buf * B_BYTES
                                                 + (kc * 3 + q) * 4096)
                                  + colhalf * 256 + lane;
                uint2 B[8];
#pragma unroll
                for (int nf = 0; nf < 8; ++nf) B[nf] = bp[nf * 32];
#pragma unroll
                for (int p = 0; p < 3 - q; ++p)
#pragma unroll
                    for (int mf = 0; mf < 2; ++mf)
#pragma unroll
                        for (int nf = 0; nf < 8; ++nf)
                            mma16816(acc[nf][mf], A[mf][p][0], A[mf][p][1],
                                     A[mf][p][2], A[mf][p][3], B[nf].x, B[nf].y);
            }
        }

        // ---- fused argmin epilogue (reference-exact rounding, tie -> lowest idx)
#pragma unroll
        for (int nf = 0; nf < 8; ++nf) {
            int cb = t * NTILE + colhalf * 64 + nf * 8 + 2 * c;
            float e0 = esq_s[cb], e1 = esq_s[cb + 1];
#pragma unroll
            for (int mf = 0; mf < 2; ++mf) {
                float k00 = fmaf(-2.f, acc[nf][mf][0], __fadd_rn(ysr[mf][0], e0));
                float k01 = fmaf(-2.f, acc[nf][mf][1], __fadd_rn(ysr[mf][0], e1));
                float k10 = fmaf(-2.f, acc[nf][mf][2], __fadd_rn(ysr[mf][1], e0));
                float k11 = fmaf(-2.f, acc[nf][mf][3], __fadd_rn(ysr[mf][1], e1));
                if (k00 < bv[mf][0]) { bv[mf][0] = k00; bc[mf][0] = cb; }
                if (k01 < bv[mf][0]) { bv[mf][0] = k01; bc[mf][0] = cb + 1; }
                if (k10 < bv[mf][1]) { bv[mf][1] = k10; bc[mf][1] = cb; }
                if (k11 < bv[mf][1]) { bv[mf][1] = k11; bc[mf][1] = cb + 1; }
            }
        }
        __syncthreads();   // buf consumed before next iteration's prefetch reuses it
    }

    // ---- merge across the 4 lanes (c) sharing each row (tie -> lowest index)
#pragma unroll
    for (int off = 1; off <= 2; off <<= 1) {
#pragma unroll
        for (int mf = 0; mf < 2; ++mf)
#pragma unroll
            for (int h = 0; h < 2; ++h) {
                float v = __shfl_xor_sync(0xffffffffu, bv[mf][h], off);
                int   cc = __shfl_xor_sync(0xffffffffu, bc[mf][h], off);
                if (v < bv[mf][h] || (v == bv[mf][h] && cc < bc[mf][h])) {
                    bv[mf][h] = v; bc[mf][h] = cc;
                }
            }
    }
    // ---- cross-column-half merge via smem
    float* bv0 = (float*)(smem + SM_MRG);
    int*   bc0 = (int*)(smem + SM_MRG + 512);
    float* bv1 = (float*)(smem + SM_MRG + 1024);
    int*   bc1 = (int*)(smem + SM_MRG + 1536);
    if (c == 0) {
#pragma unroll
        for (int mf = 0; mf < 2; ++mf)
#pragma unroll
            for (int h = 0; h < 2; ++h) {
                int r = rowid[mf][h];
                if (colhalf == 0) { bv0[r] = bv[mf][h]; bc0[r] = bc[mf][h]; }
                else              { bv1[r] = bv[mf][h]; bc1[r] = bc[mf][h]; }
            }
    }
    __syncthreads();
    if (tid < ROWS_PER_CTA) {
        float va = bv0[tid], vb = bv1[tid];
        int   ca = bc0[tid], cb2 = bc1[tid];
        int pickB = (vb < va) || (vb == va && cb2 < ca);
        cidx[tid] = pickB ? cb2 : ca;
    }
    __syncthreads();

    // ---- gather output rows from transposed codebook
    float* og = out + rowbase * D_DIM;
#pragma unroll
    for (int it = 0; it < 8; ++it) {
        int i  = tid + it * NTHREADS;
        int r  = i >> 4;
        int d0 = (i & 15) << 2;
        *(float4*)(og + r * D_DIM + d0) = *(const float4*)(g_ET + cidx[r] * D_DIM + d0);
    }
}

extern "C" void kernel_launch(void* const* d_in, const int* in_sizes, int n_in,
                              void* d_out, int out_size) {
    const float* x = (const float*)d_in[0];
    const float* E = (const float*)d_in[1];
    float* out = (float*)d_out;
    int N = in_sizes[0] / D_DIM;  // 131072

    cudaFuncSetAttribute(vq_tc, cudaFuncAttributeMaxDynamicSharedMemorySize, SM_TOTAL);
    vq_prep<<<K_DIM / 8, NTHREADS>>>(E);
    vq_prep_b<<<(NTILES * 4 * 3 * 16 * 32) / NTHREADS, NTHREADS>>>(E);
    vq_tc<<<N / ROWS_PER_CTA, NTHREADS, SM_TOTAL>>>(x, out);
}

// round 12
// speedup vs baseline: 2.0803x; 1.4996x over previous
#include <cuda_runtime.h>
#include <cuda_fp16.h>
#include <cstdint>

// vaeVectorQuantizer: x[N=131072, D=64], E[D=64, K=1024]
// mma.sync.m16n8k16.f16 path; sim = 3 limb products of 2-limb fp16 splits
// (h1e1 + h2e1 + h1e2; dropped h2e2 ~ 2^-22 => sim err ~2e-7, same class as
// the fp32 scalar kernel that measured rel_err=0.0).
// key = fmaf(-2, sim, fl(y_sq + e_sq)); y_sq/e_sq correctly rounded (double);
// ties -> lowest index. 16 warps: 4 row-groups x 4 column-quarters.

#define D_DIM 64
#define K_DIM 1024
#define ROWS_PER_CTA 128
#define NTILE 128
#define NTILES 8
#define MTHREADS 512
#define PTHREADS 256

#define PADROW 144                             // 128B data + 16B pad
#define LIMB_STRIDE (ROWS_PER_CTA * PADROW)    // 18432
#define SM_X     0
#define SM_B     (2 * LIMB_STRIDE)             // 36864
#define B_BYTES  (NTILE * 64 * 2 * 2)          // 32768 per tile (fragment-packed)
#define SM_ESQ   (SM_B + 2 * B_BYTES)          // 102400 (double buffer)
#define SM_YS    (SM_ESQ + 4096)               // 106496
#define SM_MRG   (SM_YS + 512)                 // 107008 (qv 2048 + qc 2048)
#define SM_CIDX  (SM_MRG + 4096)               // 111104
#define SM_TOTAL (SM_CIDX + 512)               // 111616

__device__ float g_esq[K_DIM];
__device__ float g_ET[K_DIM * D_DIM];             // [k][d] for coalesced gather
__device__ uint2 g_Bf[NTILES * 4 * 2 * 16 * 32];  // [t][kc][limb][nf][lane]

__device__ __forceinline__ uint32_t smem_u32(const void* p) {
    uint32_t a;
    asm("{ .reg .u64 t; cvta.to.shared.u64 t, %1; cvt.u32.u64 %0, t; }" : "=r"(a) : "l"(p));
    return a;
}
__device__ __forceinline__ void cp16(uint32_t dst, const void* src) {
    asm volatile("cp.async.cg.shared.global [%0], [%1], 16;" :: "r"(dst), "l"(src));
}
#define CP_COMMIT() asm volatile("cp.async.commit_group;" ::: "memory")
#define CP_WAIT(N)  asm volatile("cp.async.wait_group %0;" :: "n"(N) : "memory")

__device__ __forceinline__ void split2h(float f, __half& h1, __half& h2) {
    h1 = __float2half_rn(f);
    h2 = __float2half_rn(f - __half2float(h1));
}

__device__ __forceinline__ void mma16816h(float* c, uint32_t a0, uint32_t a1,
                                          uint32_t a2, uint32_t a3,
                                          uint32_t b0, uint32_t b1) {
    asm volatile(
        "mma.sync.aligned.m16n8k16.row.col.f32.f16.f16.f32 "
        "{%0,%1,%2,%3}, {%4,%5,%6,%7}, {%8,%9}, {%0,%1,%2,%3};"
        : "+f"(c[0]), "+f"(c[1]), "+f"(c[2]), "+f"(c[3])
        : "r"(a0), "r"(a1), "r"(a2), "r"(a3), "r"(b0), "r"(b1));
}

// ---------------- prep: e_sq via warp-per-code + transposed gather table ----------------
__global__ void vq_prep(const float* __restrict__ E) {
    int wid = threadIdx.x >> 5, lane = threadIdx.x & 31;
    int k = blockIdx.x * 8 + wid;
    float v0 = E[lane * K_DIM + k];
    float v1 = E[(lane + 32) * K_DIM + k];
    g_ET[k * D_DIM + lane]      = v0;
    g_ET[k * D_DIM + lane + 32] = v1;
    double s = fma((double)v0, (double)v0, (double)v1 * (double)v1);
#pragma unroll
    for (int off = 16; off >= 1; off >>= 1)
        s += __shfl_xor_sync(0xffffffffu, s, off);
    if (lane == 0) g_esq[k] = (float)s;
}

// ---------------- prep: B fp16 limbs packed in mma fragment-lane order ----------------
// Entry (t,kc,limb,nf,lane), reg m, half j holds
//   E_limb[d][code],  d = kc*16 + (lane%4)*2 + m*8 + j,  code = t*128 + nf*8 + lane/4
__global__ void vq_prep_b(const float* __restrict__ E) {
    int idx = blockIdx.x * blockDim.x + threadIdx.x;   // 32768 total
    int lane = idx & 31;
    int x1 = idx >> 5;
    int nf = x1 & 15;
    int x2 = x1 >> 4;
    int limb = x2 & 1;
    int x3 = x2 >> 1;
    int kc = x3 & 3;
    int t = x3 >> 2;

    int code = t * 128 + nf * 8 + (lane >> 2);
    int c = lane & 3;
    uint32_t r[2];
#pragma unroll
    for (int m = 0; m < 2; ++m) {
        int d0 = kc * 16 + c * 2 + m * 8;
        __half q0[2], q1[2];
        split2h(E[d0 * K_DIM + code], q0[0], q0[1]);
        split2h(E[(d0 + 1) * K_DIM + code], q1[0], q1[1]);
        __half2 pk = __halves2half2(q0[limb], q1[limb]);
        r[m] = *(uint32_t*)&pk;
    }
    g_Bf[idx] = make_uint2(r[0], r[1]);
}

// ---------------- main ----------------
__global__ __launch_bounds__(MTHREADS)
void vq_tc(const float* __restrict__ x, float* __restrict__ out) {
    extern __shared__ __align__(16) char smem[];
    const int tid = threadIdx.x;
    const int wid = tid >> 5;
    const int lane = tid & 31;
    const size_t rowbase = (size_t)blockIdx.x * ROWS_PER_CTA;

    float* esq_s = (float*)(smem + SM_ESQ);
    float* ys_sh = (float*)(smem + SM_YS);
    int*   cidx  = (int*)(smem + SM_CIDX);
    const uint32_t sB_u32 = smem_u32(smem + SM_B);

    *(float2*)(esq_s + 2 * tid) = *(const float2*)(g_esq + 2 * tid);

    // ---- prefetch B tile 0 into buffer 0 (overlaps the x-split below)
    {
        const char* src = (const char*)g_Bf;
#pragma unroll
        for (int i = 0; i < 4; ++i)
            cp16(sB_u32 + i * 8192 + tid * 16, src + i * 8192 + tid * 16);
        CP_COMMIT();
    }

    // ---- x: 2-limb fp16 split into padded smem + exact double row norms
    {
        int r = tid >> 2, dq = (tid & 3) * 16;
        const float* xr = x + (rowbase + r) * D_DIM + dq;
        char* xs = smem + SM_X + r * PADROW;
        double s = 0.0;
#pragma unroll
        for (int i = 0; i < 4; ++i) {
            float4 v = *(const float4*)(xr + 4 * i);
            int d0 = dq + 4 * i;
            float vs[4] = {v.x, v.y, v.z, v.w};
            __half p1[4], p2[4];
#pragma unroll
            for (int e = 0; e < 4; ++e) {
                split2h(vs[e], p1[e], p2[e]);
                s = fma((double)vs[e], (double)vs[e], s);
            }
#pragma unroll
            for (int h = 0; h < 2; ++h) {
                int off = (d0 + 2 * h) * 2;
                *(__half2*)(xs + off)               = __halves2half2(p1[2*h], p1[2*h+1]);
                *(__half2*)(xs + off + LIMB_STRIDE) = __halves2half2(p2[2*h], p2[2*h+1]);
            }
        }
        s += __shfl_xor_sync(0xffffffffu, s, 1);
        s += __shfl_xor_sync(0xffffffffu, s, 2);
        if ((tid & 3) == 0) ys_sh[r] = (float)s;
    }

    // 16 warps: column-quarter cq = wid>>2 (32 codes), row-group wg = wid&3 (32 rows)
    const int cq = wid >> 2;
    const int wg = wid & 3;
    const int g = lane >> 2, c = lane & 3;

    __syncthreads();   // x-split + ys visible

    int rowid[2][2];
    float ysr[2][2];
    const char* aRow[2][2];
#pragma unroll
    for (int mf = 0; mf < 2; ++mf)
#pragma unroll
        for (int h = 0; h < 2; ++h) {
            int r = wg * 32 + mf * 16 + h * 8 + g;
            rowid[mf][h] = r;
            ysr[mf][h] = ys_sh[r];
            aRow[mf][h] = smem + SM_X + r * PADROW + c * 4;
        }

    float bv[2][2] = {{3.402823466e38f, 3.402823466e38f},
                      {3.402823466e38f, 3.402823466e38f}};
    int   bc[2][2] = {{0, 0}, {0, 0}};

    for (int t = 0; t < NTILES; ++t) {
        const int buf = t & 1;
        if (t + 1 < NTILES) {
            const char* src = (const char*)g_Bf + (t + 1) * B_BYTES;
            uint32_t dst = sB_u32 + (buf ^ 1) * B_BYTES;
#pragma unroll
            for (int i = 0; i < 4; ++i)
                cp16(dst + i * 8192 + tid * 16, src + i * 8192 + tid * 16);
            CP_COMMIT();
            CP_WAIT(1);
        } else {
            CP_WAIT(0);
        }
        __syncthreads();

        float acc[4][2][4];
#pragma unroll
        for (int nf = 0; nf < 4; ++nf)
#pragma unroll
            for (int mf = 0; mf < 2; ++mf)
#pragma unroll
                for (int j = 0; j < 4; ++j) acc[nf][mf][j] = 0.f;

#pragma unroll
        for (int kc = 0; kc < 4; ++kc) {
            // ---- cache A limb fragments for this kc (loaded once)
            uint32_t A[2][2][4];
#pragma unroll
            for (int mf = 0; mf < 2; ++mf)
#pragma unroll
                for (int p = 0; p < 2; ++p) {
                    const char* a0p = aRow[mf][0] + p * LIMB_STRIDE + kc * 32;
                    const char* a1p = aRow[mf][1] + p * LIMB_STRIDE + kc * 32;
                    A[mf][p][0] = *(const uint32_t*)(a0p);
                    A[mf][p][1] = *(const uint32_t*)(a1p);
                    A[mf][p][2] = *(const uint32_t*)(a0p + 16);
                    A[mf][p][3] = *(const uint32_t*)(a1p + 16);
                }
            // ---- q=0: pairs (0,0),(1,0); q=1: pair (0,1)
#pragma unroll
            for (int q = 0; q < 2; ++q) {
                const uint2* bp = (const uint2*)(smem + SM_B + buf * B_BYTES
                                                 + (kc * 2 + q) * 4096)
                                  + cq * 128 + lane;
                uint2 B[4];
#pragma unroll
                for (int nf = 0; nf < 4; ++nf) B[nf] = bp[nf * 32];
#pragma unroll
                for (int p = 0; p < 2 - q; ++p)
#pragma unroll
                    for (int mf = 0; mf < 2; ++mf)
#pragma unroll
                        for (int nf = 0; nf < 4; ++nf)
                            mma16816h(acc[nf][mf], A[mf][p][0], A[mf][p][1],
                                      A[mf][p][2], A[mf][p][3], B[nf].x, B[nf].y);
            }
        }

        // ---- fused argmin epilogue (reference-exact rounding, tie -> lowest idx)
#pragma unroll
        for (int nf = 0; nf < 4; ++nf) {
            int cb = t * NTILE + cq * 32 + nf * 8 + 2 * c;
            float e0 = esq_s[cb], e1 = esq_s[cb + 1];
#pragma unroll
            for (int mf = 0; mf < 2; ++mf) {
                float k00 = fmaf(-2.f, acc[nf][mf][0], __fadd_rn(ysr[mf][0], e0));
                float k01 = fmaf(-2.f, acc[nf][mf][1], __fadd_rn(ysr[mf][0], e1));
                float k10 = fmaf(-2.f, acc[nf][mf][2], __fadd_rn(ysr[mf][1], e0));
                float k11 = fmaf(-2.f, acc[nf][mf][3], __fadd_rn(ysr[mf][1], e1));
                if (k00 < bv[mf][0]) { bv[mf][0] = k00; bc[mf][0] = cb; }
                if (k01 < bv[mf][0]) { bv[mf][0] = k01; bc[mf][0] = cb + 1; }
                if (k10 < bv[mf][1]) { bv[mf][1] = k10; bc[mf][1] = cb; }
                if (k11 < bv[mf][1]) { bv[mf][1] = k11; bc[mf][1] = cb + 1; }
            }
        }
        __syncthreads();   // buf consumed before next iteration's prefetch reuses it
    }

    // ---- merge across the 4 lanes (c) sharing each row (tie -> lowest index)
#pragma unroll
    for (int off = 1; off <= 2; off <<= 1) {
#pragma unroll
        for (int mf = 0; mf < 2; ++mf)
#pragma unroll
            for (int h = 0; h < 2; ++h) {
                float v = __shfl_xor_sync(0xffffffffu, bv[mf][h], off);
                int   cc = __shfl_xor_sync(0xffffffffu, bc[mf][h], off);
                if (v < bv[mf][h] || (v == bv[mf][h] && cc < bc[mf][h])) {
                    bv[mf][h] = v; bc[mf][h] = cc;
                }
            }
    }
    // ---- publish per-quarter winners, merge across the 4 column quarters
    float* qv = (float*)(smem + SM_MRG);          // [cq][row]
    int*   qc = (int*)(smem + SM_MRG + 2048);
    if (c == 0) {
#pragma unroll
        for (int mf = 0; mf < 2; ++mf)
#pragma unroll
            for (int h = 0; h < 2; ++h) {
                int r = cq * 128 + rowid[mf][h];
                qv[r] = bv[mf][h]; qc[r] = bc[mf][h];
            }
    }
    __syncthreads();
    if (tid < ROWS_PER_CTA) {
        float V = qv[tid]; int C = qc[tid];
#pragma unroll
        for (int qq = 1; qq < 4; ++qq) {
            float v = qv[qq * 128 + tid];
            int   cc = qc[qq * 128 + tid];
            if (v < V || (v == V && cc < C)) { V = v; C = cc; }
        }
        cidx[tid] = C;
    }
    __syncthreads();

    // ---- gather output rows from transposed codebook
    float* og = out + rowbase * D_DIM;
#pragma unroll
    for (int it = 0; it < 4; ++it) {
        int i  = tid + it * MTHREADS;
        int r  = i >> 4;
        int d0 = (i & 15) << 2;
        *(float4*)(og + r * D_DIM + d0) = *(const float4*)(g_ET + cidx[r] * D_DIM + d0);
    }
}

extern "C" void kernel_launch(void* const* d_in, const int* in_sizes, int n_in,
                              void* d_out, int out_size) {
    const float* x = (const float*)d_in[0];
    const float* E = (const float*)d_in[1];
    float* out = (float*)d_out;
    int N = in_sizes[0] / D_DIM;  // 131072

    cudaFuncSetAttribute(vq_tc, cudaFuncAttributeMaxDynamicSharedMemorySize, SM_TOTAL);
    vq_prep<<<K_DIM / 8, PTHREADS>>>(E);
    vq_prep_b<<<(NTILES * 4 * 2 * 16 * 32) / PTHREADS, PTHREADS>>>(E);
    vq_tc<<<N / ROWS_PER_CTA, MTHREADS, SM_TOTAL>>>(x, out);
}